// round 6
// baseline (speedup 1.0000x reference)
#include <cuda_runtime.h>
#include <math.h>
#include <stdint.h>

// Problem dims (fixed)
#define B_  64
#define T_  512
#define D_  256
#define H_  256
#define G4  1024          // 4*H
#define NBG 16            // batch groups (4 batches each) == clusters
#define CL  8             // CTAs per cluster (hidden slices of 32 units)
#define NB_SCAN (NBG*CL)  // 128 blocks

typedef unsigned long long u64;

// ---------------- device scratch ----------------
__device__ float g_Wc[G4 * D_];                 // combined weight W_ih @ W_att
__device__ float g_bc[G4];                      // combined bias
__device__ float g_vlin0[B_ * D_];              // vlin[:,0]
__device__ float g_a[B_ * T_];                  // attention scalars a[b,t]
__device__ float g_alpha[(size_t)T_ * B_ * H_]; // alpha[t][b][j]
__device__ float g_gates[(size_t)T_ * B_ * G4]; // input gates [t][b][grow]

// ---------------- helpers ----------------
__device__ __forceinline__ float sigm(float x) { return 1.0f / (1.0f + expf(-x)); }

__device__ __forceinline__ u64 pack2(float x, float y) {
    u64 r;
    asm("mov.b64 %0, {%1, %2};" : "=l"(r) : "f"(x), "f"(y));
    return r;
}
__device__ __forceinline__ u64 fma2(u64 a, u64 b, u64 c) {
    u64 d;
    asm("fma.rn.f32x2 %0, %1, %2, %3;" : "=l"(d) : "l"(a), "l"(b), "l"(c));
    return d;
}
__device__ __forceinline__ float2 unpack2(u64 v) {
    float2 f;
    asm("mov.b64 {%0, %1}, %2;" : "=f"(f.x), "=f"(f.y) : "l"(v));
    return f;
}
__device__ __forceinline__ uint32_t smem_u32(const void* p) {
    uint32_t a;
    asm("{ .reg .u64 t; cvta.to.shared.u64 t, %1; cvt.u32.u64 %0, t; }" : "=r"(a) : "l"(p));
    return a;
}

// ---------------- kernel: Wc = W_ih @ W_att ----------------
__global__ void k_wc(const float* __restrict__ W_ih, const float* __restrict__ W_att) {
    int g = blockIdx.x;
    int k = threadIdx.x;
    __shared__ float wrow[D_];
    wrow[threadIdx.x] = W_ih[g * D_ + threadIdx.x];
    __syncthreads();
    float acc = 0.f;
#pragma unroll 8
    for (int d = 0; d < D_; d++) acc += wrow[d] * W_att[d * D_ + k];
    g_Wc[g * D_ + k] = acc;
}

// ---------------- kernel: bc = W_ih @ b_att + b_ih + b_hh ----------------
__global__ void k_bc(const float* __restrict__ W_ih, const float* __restrict__ b_att,
                     const float* __restrict__ b_ih, const float* __restrict__ b_hh) {
    __shared__ float ba[D_];
    if (threadIdx.x < D_) ba[threadIdx.x] = b_att[threadIdx.x];
    __syncthreads();
    int g = blockIdx.x * blockDim.x + threadIdx.x;
    if (g >= G4) return;
    float acc = b_ih[g] + b_hh[g];
#pragma unroll 8
    for (int d = 0; d < D_; d++) acc += W_ih[g * D_ + d] * ba[d];
    g_bc[g] = acc;
}

// ---------------- kernel: vlin0[b,:] = values[b,0,:] @ W_att^T + b_att ----------------
__global__ void k_vlin0(const float* __restrict__ values, const float* __restrict__ W_att,
                        const float* __restrict__ b_att) {
    int b = blockIdx.x;
    int d = threadIdx.x;
    __shared__ float v[D_];
    v[threadIdx.x] = values[(size_t)b * T_ * D_ + threadIdx.x];
    __syncthreads();
    float acc = b_att[d];
#pragma unroll 8
    for (int k = 0; k < D_; k++) acc += v[k] * W_att[d * D_ + k];
    g_vlin0[b * D_ + d] = acc;
}

// ---------------- kernel: a[b,t] = sigmoid(vlin0[b] . values[b,t]) ----------------
__global__ void k_a(const float* __restrict__ values) {
    int w = (blockIdx.x * blockDim.x + threadIdx.x) >> 5;
    int lane = threadIdx.x & 31;
    int b = w >> 9, t = w & (T_ - 1);
    const float* vp = values + ((size_t)b * T_ + t) * D_;
    const float* lp = g_vlin0 + b * D_;
    float acc = 0.f;
#pragma unroll
    for (int k = lane; k < D_; k += 32) acc += vp[k] * lp[k];
#pragma unroll
    for (int off = 16; off; off >>= 1) acc += __shfl_down_sync(0xffffffffu, acc, off);
    if (lane == 0) g_a[w] = sigm(acc);
}

// ---------------- kernel: alpha[t][b][d] = a[b,t] / log(e + cumsum(Deltas)[b,t,d]) ----
__global__ void k_alpha(const float* __restrict__ Deltas) {
    int b = blockIdx.x;
    int d = threadIdx.x;
    const float* dp = Deltas + (size_t)b * T_ * D_ + d;
    float acc = 0.f;
    for (int t = 0; t < T_; t++) {
        acc += dp[(size_t)t * D_];
        float av = g_a[b * T_ + t];
        g_alpha[((size_t)t * B_ + b) * H_ + d] = av / logf(2.718281828459045f + acc);
    }
}

// ---------------- big GEMM: gates[t][b][g] = values[b,t,:].Wc[g,:] + bc[g] ----------
// Tile: (64 batch x 2 t) rows x 128 n per block, 256 threads, 8x8 microtile
// (split 4+4 for conflict-free LDS). grid (T_/2, 8) = 2048 blocks.
// Row index r = tt*64 + b. k staged in 16-wide chunks, register prefetch.
#define PA 132   // smem row pitch (floats), float4-aligned
__global__ __launch_bounds__(256) void k_gemm(const float* __restrict__ values) {
    int t0 = blockIdx.x * 2;
    int n0 = blockIdx.y * 128;

    __shared__ float As[16 * PA];   // [k][r]  r = tt*64 + b
    __shared__ float Bs[16 * PA];   // [k][n]

    int tid = threadIdx.x;
    int tx = tid & 15;              // row quad group
    int ty = tid >> 4;              // n quad group

    // loader: tid<128 -> A row r=tid; tid>=128 -> B row (n0 + tid-128)
    const float* gp;
    float* scol;
    {
        int r = tid & 127;
        if (tid < 128) {
            int b = r & 63, tt = r >> 6;
            gp = values + ((size_t)b * T_ + t0 + tt) * D_;
            scol = As + r;
        } else {
            gp = g_Wc + (size_t)(n0 + r) * D_;
            scol = Bs + r;
        }
    }

    float4 pf0 = ((const float4*)gp)[0];
    float4 pf1 = ((const float4*)gp)[1];
    float4 pf2 = ((const float4*)gp)[2];
    float4 pf3 = ((const float4*)gp)[3];

    u64 acc[2][4][4];               // [rowgrp(tt)][i][ngrp*2 + pair]
#pragma unroll
    for (int a = 0; a < 2; a++)
#pragma unroll
        for (int i = 0; i < 4; i++)
#pragma unroll
            for (int j = 0; j < 4; j++) acc[a][i][j] = 0ull;

    for (int c = 0; c < 16; c++) {
        __syncthreads();
        scol[ 0 * PA] = pf0.x; scol[ 1 * PA] = pf0.y; scol[ 2 * PA] = pf0.z; scol[ 3 * PA] = pf0.w;
        scol[ 4 * PA] = pf1.x; scol[ 5 * PA] = pf1.y; scol[ 6 * PA] = pf1.z; scol[ 7 * PA] = pf1.w;
        scol[ 8 * PA] = pf2.x; scol[ 9 * PA] = pf2.y; scol[10 * PA] = pf2.z; scol[11 * PA] = pf2.w;
        scol[12 * PA] = pf3.x; scol[13 * PA] = pf3.y; scol[14 * PA] = pf3.z; scol[15 * PA] = pf3.w;
        __syncthreads();

        if (c < 15) {
            const float* np = gp + (c + 1) * 16;
            pf0 = ((const float4*)np)[0];
            pf1 = ((const float4*)np)[1];
            pf2 = ((const float4*)np)[2];
            pf3 = ((const float4*)np)[3];
        }

#pragma unroll
        for (int k = 0; k < 16; k++) {
            float4 a0 = *(const float4*)&As[k * PA + 4 * tx];        // tt=0 rows
            float4 a1 = *(const float4*)&As[k * PA + 64 + 4 * tx];   // tt=1 rows
            const float* bp = &Bs[k * PA + 4 * ty];
            u64 b00 = *(const u64*)(bp);        // n0+4ty, +1
            u64 b01 = *(const u64*)(bp + 2);    // +2, +3
            u64 b10 = *(const u64*)(bp + 64);   // n0+64+4ty
            u64 b11 = *(const u64*)(bp + 66);

            u64 p;
            p = pack2(a0.x, a0.x);
            acc[0][0][0] = fma2(p, b00, acc[0][0][0]); acc[0][0][1] = fma2(p, b01, acc[0][0][1]);
            acc[0][0][2] = fma2(p, b10, acc[0][0][2]); acc[0][0][3] = fma2(p, b11, acc[0][0][3]);
            p = pack2(a0.y, a0.y);
            acc[0][1][0] = fma2(p, b00, acc[0][1][0]); acc[0][1][1] = fma2(p, b01, acc[0][1][1]);
            acc[0][1][2] = fma2(p, b10, acc[0][1][2]); acc[0][1][3] = fma2(p, b11, acc[0][1][3]);
            p = pack2(a0.z, a0.z);
            acc[0][2][0] = fma2(p, b00, acc[0][2][0]); acc[0][2][1] = fma2(p, b01, acc[0][2][1]);
            acc[0][2][2] = fma2(p, b10, acc[0][2][2]); acc[0][2][3] = fma2(p, b11, acc[0][2][3]);
            p = pack2(a0.w, a0.w);
            acc[0][3][0] = fma2(p, b00, acc[0][3][0]); acc[0][3][1] = fma2(p, b01, acc[0][3][1]);
            acc[0][3][2] = fma2(p, b10, acc[0][3][2]); acc[0][3][3] = fma2(p, b11, acc[0][3][3]);
            p = pack2(a1.x, a1.x);
            acc[1][0][0] = fma2(p, b00, acc[1][0][0]); acc[1][0][1] = fma2(p, b01, acc[1][0][1]);
            acc[1][0][2] = fma2(p, b10, acc[1][0][2]); acc[1][0][3] = fma2(p, b11, acc[1][0][3]);
            p = pack2(a1.y, a1.y);
            acc[1][1][0] = fma2(p, b00, acc[1][1][0]); acc[1][1][1] = fma2(p, b01, acc[1][1][1]);
            acc[1][1][2] = fma2(p, b10, acc[1][1][2]); acc[1][1][3] = fma2(p, b11, acc[1][1][3]);
            p = pack2(a1.z, a1.z);
            acc[1][2][0] = fma2(p, b00, acc[1][2][0]); acc[1][2][1] = fma2(p, b01, acc[1][2][1]);
            acc[1][2][2] = fma2(p, b10, acc[1][2][2]); acc[1][2][3] = fma2(p, b11, acc[1][2][3]);
            p = pack2(a1.w, a1.w);
            acc[1][3][0] = fma2(p, b00, acc[1][3][0]); acc[1][3][1] = fma2(p, b01, acc[1][3][1]);
            acc[1][3][2] = fma2(p, b10, acc[1][3][2]); acc[1][3][3] = fma2(p, b11, acc[1][3][3]);
        }
    }

    // epilogue: gates[t][b][n], add bias
    float4 biasA = *(const float4*)&g_bc[n0 + 4 * ty];
    float4 biasB = *(const float4*)&g_bc[n0 + 64 + 4 * ty];
#pragma unroll
    for (int tt = 0; tt < 2; tt++) {
#pragma unroll
        for (int i = 0; i < 4; i++) {
            int b = 4 * tx + i;
            float* op = g_gates + ((size_t)(t0 + tt) * B_ + b) * G4 + n0;
            float2 p0 = unpack2(acc[tt][i][0]);
            float2 p1 = unpack2(acc[tt][i][1]);
            float2 p2 = unpack2(acc[tt][i][2]);
            float2 p3 = unpack2(acc[tt][i][3]);
            *(float4*)&op[4 * ty] =
                make_float4(p0.x + biasA.x, p0.y + biasA.y, p1.x + biasA.z, p1.y + biasA.w);
            *(float4*)&op[64 + 4 * ty] =
                make_float4(p2.x + biasB.x, p2.y + biasB.y, p3.x + biasB.z, p3.y + biasB.w);
        }
    }
}

// ---------------- persistent scan kernel (clustered) ----------------
// 128 blocks = 16 clusters of 8. Cluster g owns batches 4g..4g+3; CTA rank s owns
// hidden units s*32..s*32+31. h exchanged via DSMEM (st.shared::cluster into all
// 8 peers' double-buffered h arrays), one barrier.cluster arrive/wait per step.
#define PSP 34  // psum row pitch (even -> 8B-aligned u64 stores)
__global__ __launch_bounds__(256, 1) __cluster_dims__(CL, 1, 1)
void k_scan(const float* __restrict__ Whh, float* __restrict__ out) {
    extern __shared__ float sm[];
    float* w_s  = sm;                    // 32768 floats  W slice transposed [k][r]
    float* hb0  = sm + 32768;            // 1024 floats   h buffer 0, [j][b] == [k][b]
    float* hb1  = hb0 + 1024;            // 1024 floats   h buffer 1
    float* psum = hb1 + 1024;            // 128*PSP + 32  [r][ks*4 + b]

    int tid = threadIdx.x;
    int bid = blockIdx.x;
    int g = bid >> 3;
    uint32_t s;
    asm("mov.u32 %0, %%cluster_ctarank;" : "=r"(s));

    // preload W slice transposed: w_s[k*128 + r], r = q*32+jl <-> grow = q*256 + s*32 + jl
    for (int i = tid; i < 128 * 256; i += 256) {
        int r = i >> 8, k = i & 255;
        int grow = ((r >> 5) << 8) + ((int)s << 5) + (r & 31);
        w_s[k * 128 + r] = Whh[grow * 256 + k];
    }

    // dot identity: 8 k-chunks x 32 row-quads
    int ks = tid >> 5, rq = tid & 31;
    const float* wp = w_s + (ks * 32) * 128 + 4 * rq;

    // update identity (tid < 128)
    int ub = tid >> 5;            // 0..3 (batch-local)
    int jl = tid & 31;
    int bg = g * 4 + ub;          // global batch
    int jglob = (int)s * 32 + jl; // global hidden unit

    // remote (cluster) addresses of my h slot in both buffers, all 8 CTAs
    uint32_t base = smem_u32(sm);
    uint32_t off0 = base + (uint32_t)(32768 + jglob * 4 + ub) * 4u;
    uint32_t off1 = off0 + 1024u * 4u;
    uint32_t ra0[CL], ra1[CL];
#pragma unroll
    for (int r = 0; r < CL; r++) {
        asm("mapa.shared::cluster.u32 %0, %1, %2;" : "=r"(ra0[r]) : "r"(off0), "r"(r));
        asm("mapa.shared::cluster.u32 %0, %1, %2;" : "=r"(ra1[r]) : "r"(off1), "r"(r));
    }

    float c_reg = 0.f, c0_reg = 0.f;
    __syncthreads();

    // ---- prologue t = 0 (h=0, c=0; carry c stays zero — faithful quirk) ----
    if (tid < 128) {
        const float* g0 = g_gates + (size_t)bg * G4;
        float zi = g0[0 * H_ + jglob];
        float zg = g0[2 * H_ + jglob];
        float zo = g0[3 * H_ + jglob];
        c0_reg = sigm(zi) * tanhf(zg);
        float h1v = sigm(zo) * tanhf(c0_reg);
#pragma unroll
        for (int r = 0; r < CL; r++)
            asm volatile("st.shared::cluster.f32 [%0], %1;" :: "r"(ra0[r]), "f"(h1v) : "memory");
        out[(size_t)bg * (T_ * H_) + jglob] = h1v;
    }
    asm volatile("barrier.cluster.arrive.aligned;" ::: "memory");

    for (int t = 1; t < T_; t++) {
        // prefetch input gates + alpha (independent of cluster barrier)
        float gin0 = 0.f, gin1 = 0.f, gin2 = 0.f, gin3 = 0.f, al = 0.f;
        if (tid < 128) {
            const float* gt = g_gates + ((size_t)t * B_ + bg) * G4;
            gin0 = gt[0 * H_ + jglob];
            gin1 = gt[1 * H_ + jglob];
            gin2 = gt[2 * H_ + jglob];
            gin3 = gt[3 * H_ + jglob];
            al   = g_alpha[((size_t)t * B_ + bg) * H_ + jglob];
        }

        // wait for h(t-1) to be fully written into my read buffer by all peers
        asm volatile("barrier.cluster.wait.aligned;" ::: "memory");

        const float* hp = ((t & 1) ? hb0 : hb1) + (ks * 32) * 4;

        // dot: 4 rows x 4 batches x 32 k per thread, FFMA2 over batch pairs
        {
            u64 a00 = 0, a01 = 0, a10 = 0, a11 = 0;
            u64 a20 = 0, a21 = 0, a30 = 0, a31 = 0;
#pragma unroll 8
            for (int k = 0; k < 32; k++) {
                float4 w4 = *(const float4*)(wp + k * 128);
                u64 h01 = *(const u64*)(hp + k * 4);
                u64 h23 = *(const u64*)(hp + k * 4 + 2);
                u64 w0 = pack2(w4.x, w4.x);
                u64 w1 = pack2(w4.y, w4.y);
                u64 w2 = pack2(w4.z, w4.z);
                u64 w3 = pack2(w4.w, w4.w);
                a00 = fma2(w0, h01, a00); a01 = fma2(w0, h23, a01);
                a10 = fma2(w1, h01, a10); a11 = fma2(w1, h23, a11);
                a20 = fma2(w2, h01, a20); a21 = fma2(w2, h23, a21);
                a30 = fma2(w3, h01, a30); a31 = fma2(w3, h23, a31);
            }
            int r0 = 4 * rq;
            *(u64*)&psum[(r0 + 0) * PSP + ks * 4]     = a00;
            *(u64*)&psum[(r0 + 0) * PSP + ks * 4 + 2] = a01;
            *(u64*)&psum[(r0 + 1) * PSP + ks * 4]     = a10;
            *(u64*)&psum[(r0 + 1) * PSP + ks * 4 + 2] = a11;
            *(u64*)&psum[(r0 + 2) * PSP + ks * 4]     = a20;
            *(u64*)&psum[(r0 + 2) * PSP + ks * 4 + 2] = a21;
            *(u64*)&psum[(r0 + 3) * PSP + ks * 4]     = a30;
            *(u64*)&psum[(r0 + 3) * PSP + ks * 4 + 2] = a31;
        }
        __syncthreads();

        // cell update: 128 threads, one per (batch, unit); write h(t) to all peers
        if (tid < 128) {
            float zi = gin0, zf = gin1, zg = gin2, zo = gin3;
            const float* pi = psum + (0 * 32 + jl) * PSP + ub;
            const float* pf = psum + (1 * 32 + jl) * PSP + ub;
            const float* pg = psum + (2 * 32 + jl) * PSP + ub;
            const float* po = psum + (3 * 32 + jl) * PSP + ub;
#pragma unroll
            for (int kss = 0; kss < 8; kss++) {
                zi += pi[kss * 4];
                zf += pf[kss * 4];
                zg += pg[kss * 4];
                zo += po[kss * 4];
            }
            float c = al * c0_reg + (1.f - al) * c_reg;
            c = sigm(zf) * c + sigm(zi) * tanhf(zg);
            c_reg = c;
            float h = sigm(zo) * tanhf(c);
            if (t < T_ - 1) {
                const uint32_t* ra = (t & 1) ? ra1 : ra0;
#pragma unroll
                for (int r = 0; r < CL; r++)
                    asm volatile("st.shared::cluster.f32 [%0], %1;" :: "r"(ra[r]), "f"(h) : "memory");
            }
            out[(size_t)bg * (T_ * H_) + (size_t)t * H_ + jglob] = h;
        }
        __syncthreads();
        if (t < T_ - 1)
            asm volatile("barrier.cluster.arrive.aligned;" ::: "memory");
    }
}

// ---------------- launch ----------------
extern "C" void kernel_launch(void* const* d_in, const int* in_sizes, int n_in,
                              void* d_out, int out_size) {
    (void)in_sizes; (void)n_in; (void)out_size;
    const float* values = (const float*)d_in[0];
    const float* Deltas = (const float*)d_in[1];
    const float* W_att  = (const float*)d_in[2];
    const float* b_att  = (const float*)d_in[3];
    const float* W_ih   = (const float*)d_in[4];
    const float* W_hh   = (const float*)d_in[5];
    const float* b_ih   = (const float*)d_in[6];
    const float* b_hh   = (const float*)d_in[7];
    float* out = (float*)d_out;

    size_t smem = (size_t)(32768 + 2 * 1024 + 128 * PSP + 32) * 4;  // 156800 B
    cudaFuncSetAttribute(k_scan, cudaFuncAttributeMaxDynamicSharedMemorySize, (int)smem);
    cudaFuncSetAttribute(k_scan, cudaFuncAttributeNonPortableClusterSizeAllowed, 1);

    k_wc<<<G4, D_>>>(W_ih, W_att);
    k_bc<<<G4 / 256, 256>>>(W_ih, b_att, b_ih, b_hh);
    k_vlin0<<<B_, D_>>>(values, W_att, b_att);
    k_gemm<<<dim3(T_ / 2, G4 / 128), 256>>>(values);
    k_a<<<(B_ * T_ * 32) / 256, 256>>>(values);
    k_alpha<<<B_, D_>>>(Deltas);
    k_scan<<<NB_SCAN, 256, smem>>>(W_hh, out);
}